// round 15
// baseline (speedup 1.0000x reference)
#include <cuda_runtime.h>
#include <cuda_fp16.h>

#define IN_F   128
#define HEADS  8
#define HC     16    // HEADS * OUT_C
#define NMAX   100000
#define NPC    256   // nodes per CTA (= threads)
#define XPADH  136   // halves per xh row (272B: conflict-free ldmatrix stride)

// Static scratch (no allocations allowed)
// g_pack[n] = 64B: 4 q-blocks {asrc[2q], asrc[2q+1] fp32, h[4q..4q+3] fp16}
__device__ __align__(128) uint4 g_pack[NMAX * 4];
__device__ __align__(128) float g_adst[NMAX * HEADS]; // 32B per node row
__device__ __align__(16)  float g_acc[NMAX * 24];     // per node: S[16] then Z[8]

// FFMA-only exp: exp(x) = 2^(x*log2e). |x| small here, rel err ~2e-6.
__device__ __forceinline__ float fexp(float x) {
    float y = x * 1.44269504f;
    float r = rintf(y);
    float f = y - r;
    float p = 1.3333558e-3f;
    p = fmaf(p, f, 9.6181291e-3f);
    p = fmaf(p, f, 5.5504109e-2f);
    p = fmaf(p, f, 2.4022651e-1f);
    p = fmaf(p, f, 6.9314718e-1f);
    p = fmaf(p, f, 1.0f);
    return __int_as_float(__float_as_int(p) + ((int)r << 23));
}

__device__ __forceinline__ float leaky(float l) {
    return fmaxf(l, 0.f) + 0.2f * fminf(l, 0.f);
}

// -------- Kernel 1: node transform via HMMA (m16n8k16, fp16 in / fp32 acc) ----
__global__ __launch_bounds__(256) void node_kernel(const float* __restrict__ x,
                                                   const float* __restrict__ W,
                                                   const float* __restrict__ att_src,
                                                   const float* __restrict__ att_dst,
                                                   int N) {
    __shared__ __align__(16) __half xh[NPC * XPADH];   // 69.6KB: x tile fp16
    __shared__ __align__(16) __half WhT[16 * XPADH];   // 4.3KB: W^T fp16
    __shared__ float s_att[2 * HC];

    int tid = threadIdx.x;
    int lane = tid & 31;
    int warp = tid >> 5;
    int n0 = blockIdx.x * NPC;
    int valid = min(NPC, N - n0);

    // W^T fp16: WhT[j][k] = W[k*16+j]
    for (int i = tid; i < 16 * IN_F; i += 256) {
        int j = i >> 7, k = i & 127;
        WhT[j * XPADH + k] = __float2half(W[k * HC + j]);
    }
    if (tid < HC) { s_att[tid] = att_src[tid]; s_att[HC + tid] = att_dst[tid]; }

    // Stage x as fp16 (coalesced 32B loads, cvt, 16B stores). Zero-fill tail.
    for (int c = tid; c < NPC * 16; c += 256) {
        int r = c >> 4, c8 = c & 15;
        uint4 st;
        if (r < valid) {
            const float4* xp = (const float4*)(x + (size_t)(n0 + r) * IN_F + c8 * 8);
            float4 v0 = xp[0], v1 = xp[1];
            __half2 h0 = __floats2half2_rn(v0.x, v0.y);
            __half2 h1 = __floats2half2_rn(v0.z, v0.w);
            __half2 h2 = __floats2half2_rn(v1.x, v1.y);
            __half2 h3 = __floats2half2_rn(v1.z, v1.w);
            st.x = *(unsigned*)&h0; st.y = *(unsigned*)&h1;
            st.z = *(unsigned*)&h2; st.w = *(unsigned*)&h3;
        } else {
            st = make_uint4(0, 0, 0, 0);
        }
        *(uint4*)&xh[r * XPADH + c8 * 8] = st;
    }
    __syncthreads();

    // B fragments (register-resident): b[nt][ks][2]
    int g = lane >> 2, tig = lane & 3;
    unsigned bfr[2][8][2];
#pragma unroll
    for (int nt = 0; nt < 2; nt++)
#pragma unroll
        for (int ks = 0; ks < 8; ks++) {
            bfr[nt][ks][0] = *(const unsigned*)&WhT[(nt * 8 + g) * XPADH + ks * 16 + 2 * tig];
            bfr[nt][ks][1] = *(const unsigned*)&WhT[(nt * 8 + g) * XPADH + ks * 16 + 8 + 2 * tig];
        }

    float acc[2][2][4];
#pragma unroll
    for (int mt = 0; mt < 2; mt++)
#pragma unroll
        for (int nt = 0; nt < 2; nt++)
#pragma unroll
            for (int i = 0; i < 4; i++) acc[mt][nt][i] = 0.f;

    int arow = lane & 15;            // lanes 0-15: rows 0-15 at koff 0
    int koff = (lane >> 4) * 8;      // lanes 16-31: rows 0-15 at koff 8

#pragma unroll
    for (int ks = 0; ks < 8; ks++) {
        unsigned a[2][4];
#pragma unroll
        for (int mt = 0; mt < 2; mt++) {
            unsigned addr = (unsigned)__cvta_generic_to_shared(
                &xh[(warp * 32 + mt * 16 + arow) * XPADH + ks * 16 + koff]);
            asm volatile("ldmatrix.sync.aligned.m8n8.x4.shared.b16 {%0,%1,%2,%3}, [%4];"
                         : "=r"(a[mt][0]), "=r"(a[mt][1]), "=r"(a[mt][2]), "=r"(a[mt][3])
                         : "r"(addr));
        }
#pragma unroll
        for (int mt = 0; mt < 2; mt++)
#pragma unroll
            for (int nt = 0; nt < 2; nt++) {
                asm volatile(
                    "mma.sync.aligned.m16n8k16.row.col.f32.f16.f16.f32 "
                    "{%0,%1,%2,%3}, {%4,%5,%6,%7}, {%8,%9}, {%0,%1,%2,%3};"
                    : "+f"(acc[mt][nt][0]), "+f"(acc[mt][nt][1]),
                      "+f"(acc[mt][nt][2]), "+f"(acc[mt][nt][3])
                    : "r"(a[mt][0]), "r"(a[mt][1]), "r"(a[mt][2]), "r"(a[mt][3]),
                      "r"(bfr[nt][ks][0]), "r"(bfr[nt][ks][1]));
            }
    }

    // Epilogue: warp-private D buffer overlaid on the warp's own xh rows.
    float* Db = (float*)&xh[warp * 32 * XPADH];   // 32x17 floats fits in 8704B
    __syncwarp();
#pragma unroll
    for (int mt = 0; mt < 2; mt++)
#pragma unroll
        for (int nt = 0; nt < 2; nt++) {
            int col = nt * 8 + 2 * tig;
            Db[(mt * 16 + g) * 17 + col]         = acc[mt][nt][0];
            Db[(mt * 16 + g) * 17 + col + 1]     = acc[mt][nt][1];
            Db[(mt * 16 + g + 8) * 17 + col]     = acc[mt][nt][2];
            Db[(mt * 16 + g + 8) * 17 + col + 1] = acc[mt][nt][3];
        }
    __syncwarp();

    int n = n0 + warp * 32 + lane;
    if (n >= N) return;

    float av[HC];
#pragma unroll
    for (int c = 0; c < HC; c++) av[c] = Db[lane * 17 + c];

    float as[HEADS], ad[HEADS];
#pragma unroll
    for (int hh = 0; hh < HEADS; hh++) {
        as[hh] = av[2 * hh] * s_att[2 * hh] + av[2 * hh + 1] * s_att[2 * hh + 1];
        ad[hh] = av[2 * hh] * s_att[HC + 2 * hh] + av[2 * hh + 1] * s_att[HC + 2 * hh + 1];
    }

    // packed src struct: per q-block {asrc[2q], asrc[2q+1], h[4q..4q+3] fp16}
#pragma unroll
    for (int q = 0; q < 4; q++) {
        uint4 pk;
        pk.x = __float_as_uint(as[2 * q]);
        pk.y = __float_as_uint(as[2 * q + 1]);
        __half2 t0 = __floats2half2_rn(av[4 * q],     av[4 * q + 1]);
        __half2 t1 = __floats2half2_rn(av[4 * q + 2], av[4 * q + 3]);
        pk.z = *(unsigned*)&t0;
        pk.w = *(unsigned*)&t1;
        g_pack[(size_t)n * 4 + q] = pk;
    }

    *(float4*)(g_adst + (size_t)n * HEADS)     = make_float4(ad[0], ad[1], ad[2], ad[3]);
    *(float4*)(g_adst + (size_t)n * HEADS + 4) = make_float4(ad[4], ad[5], ad[6], ad[7]);

    float p[HEADS];
#pragma unroll
    for (int hh = 0; hh < HEADS; hh++) p[hh] = fexp(leaky(as[hh] + ad[hh]));

    float* accp = g_acc + (size_t)n * 24;
#pragma unroll
    for (int q = 0; q < 4; q++) {
        *(float4*)(accp + 4 * q) = make_float4(p[2 * q] * av[4 * q],
                                               p[2 * q] * av[4 * q + 1],
                                               p[2 * q + 1] * av[4 * q + 2],
                                               p[2 * q + 1] * av[4 * q + 3]);
    }
    *(float4*)(accp + 16) = make_float4(p[0], p[1], p[2], p[3]);
    *(float4*)(accp + 20) = make_float4(p[4], p[5], p[6], p[7]);
}

// -------- Kernel 2: per-edge gather + fast-exp + scatter (vector red) --------
// Four threads per edge: thread q handles heads 2q, 2q+1. One 16B src gather.
__global__ __launch_bounds__(256) void edge_kernel(const int* __restrict__ ei, int E) {
    int t = blockIdx.x * blockDim.x + threadIdx.x;
    int e = t >> 2;
    if (e >= E) return;
    int q = t & 3;
    int s = __ldg(&ei[e]);
    int d = __ldg(&ei[E + e]);

    uint4 pk = *(const uint4*)(g_pack + (size_t)s * 4 + q);
    float2 b = *(const float2*)(g_adst + (size_t)d * HEADS + 2 * q);
    float p0 = fexp(leaky(__uint_as_float(pk.x) + b.x));
    float p1 = fexp(leaky(__uint_as_float(pk.y) + b.y));
    float2 f01 = __half22float2(*(__half2*)&pk.z);
    float2 f23 = __half22float2(*(__half2*)&pk.w);

    float* accp = g_acc + (size_t)d * 24;
    asm volatile("red.global.add.v4.f32 [%0], {%1, %2, %3, %4};"
                 :: "l"(accp + 4 * q),
                    "f"(p0 * f01.x), "f"(p0 * f01.y),
                    "f"(p1 * f23.x), "f"(p1 * f23.y) : "memory");

    float pp0 = __shfl_xor_sync(0xffffffffu, p0, 1);
    float pp1 = __shfl_xor_sync(0xffffffffu, p1, 1);
    if ((q & 1) == 0) {
        asm volatile("red.global.add.v4.f32 [%0], {%1, %2, %3, %4};"
                     :: "l"(accp + 16 + 2 * q),
                        "f"(p0), "f"(p1), "f"(pp0), "f"(pp1) : "memory");
    }
}

// -------- Kernel 3: normalize + bias + FC --------
__global__ __launch_bounds__(256) void out_kernel(const float* __restrict__ bias_gat,
                                                  const float* __restrict__ W_fc,
                                                  const float* __restrict__ b_fc,
                                                  float* __restrict__ out, int N) {
    int n = blockIdx.x * blockDim.x + threadIdx.x;
    if (n >= N) return;
    const float4* ap = (const float4*)(g_acc + (size_t)n * 24);
    float4 s0 = ap[0], s1 = ap[1], s2 = ap[2], s3 = ap[3];
    float4 z0 = ap[4], z1 = ap[5];
    float S[16] = { s0.x, s0.y, s0.z, s0.w, s1.x, s1.y, s1.z, s1.w,
                    s2.x, s2.y, s2.z, s2.w, s3.x, s3.y, s3.z, s3.w };
    float Z[8]  = { z0.x, z0.y, z0.z, z0.w, z1.x, z1.y, z1.z, z1.w };

    float o0 = __ldg(&b_fc[0]), o1 = __ldg(&b_fc[1]);
#pragma unroll
    for (int hh = 0; hh < 8; hh++) {
        float inv = 1.f / Z[hh];   // Z >= exp(self-loop) > 0 always
        float g0 = S[2 * hh] * inv + __ldg(&bias_gat[2 * hh]);
        float g1 = S[2 * hh + 1] * inv + __ldg(&bias_gat[2 * hh + 1]);
        o0 += g0 * __ldg(&W_fc[(2 * hh) * 2 + 0]) + g1 * __ldg(&W_fc[(2 * hh + 1) * 2 + 0]);
        o1 += g0 * __ldg(&W_fc[(2 * hh) * 2 + 1]) + g1 * __ldg(&W_fc[(2 * hh + 1) * 2 + 1]);
    }
    ((float2*)out)[n] = make_float2(o0, o1);
}

extern "C" void kernel_launch(void* const* d_in, const int* in_sizes, int n_in,
                              void* d_out, int out_size) {
    const float* x        = (const float*)d_in[0];
    const int*   ei       = (const int*)d_in[1];   // int32 (JAX x64 disabled)
    // d_in[2] = edge_attr: unused (GATConv built without edge_dim)
    const float* W        = (const float*)d_in[3];
    const float* att_src  = (const float*)d_in[4];
    const float* att_dst  = (const float*)d_in[5];
    const float* bias_gat = (const float*)d_in[6];
    const float* W_fc     = (const float*)d_in[7];
    const float* b_fc     = (const float*)d_in[8];

    int N = in_sizes[0] / IN_F;
    int E = in_sizes[1] / 2;

    node_kernel<<<(N + NPC - 1) / NPC, 256>>>(x, W, att_src, att_dst, N);
    long long tthreads = 4LL * E;
    edge_kernel<<<(int)((tthreads + 255) / 256), 256>>>(ei, E);
    out_kernel<<<(N + 255) / 256, 256>>>(bias_gat, W_fc, b_fc, (float*)d_out, N);
}

// round 16
// speedup vs baseline: 1.4747x; 1.4747x over previous
#include <cuda_runtime.h>
#include <cuda_fp16.h>

#define IN_F   128
#define HEADS  8
#define HC     16   // HEADS * OUT_C
#define NMAX   100000
#define NT     128   // threads (=nodes) per CTA in node_kernel
#define KT     32    // k-tile width
#define XPAD   36    // padded row stride (floats); 144B = 9*16B, cp.async-aligned
#define NTILES (IN_F / KT)

// Static scratch (no allocations allowed)
// g_pack[n] = 64B: 4 q-blocks {asrc[2q], asrc[2q+1] fp32, h[4q..4q+3] fp16}
__device__ __align__(128) uint4 g_pack[NMAX * 4];
__device__ __align__(128) float g_adst[NMAX * HEADS]; // 32B per node row
__device__ __align__(16)  float g_acc[NMAX * 24];     // per node: S[16] then Z[8]

// FFMA-only exp: exp(x) = 2^(x*log2e). |x| small here, rel err ~2e-6.
__device__ __forceinline__ float fexp(float x) {
    float y = x * 1.44269504f;
    float r = rintf(y);
    float f = y - r;
    float p = 1.3333558e-3f;
    p = fmaf(p, f, 9.6181291e-3f);
    p = fmaf(p, f, 5.5504109e-2f);
    p = fmaf(p, f, 2.4022651e-1f);
    p = fmaf(p, f, 6.9314718e-1f);
    p = fmaf(p, f, 1.0f);
    return __int_as_float(__float_as_int(p) + ((int)r << 23));
}

__device__ __forceinline__ float leaky(float l) {
    return fmaxf(l, 0.f) + 0.2f * fminf(l, 0.f);
}

__device__ __forceinline__ void cp16(unsigned dst, const void* src) {
    asm volatile("cp.async.ca.shared.global [%0], [%1], 16;" :: "r"(dst), "l"(src) : "memory");
}
__device__ __forceinline__ void cp_commit() {
    asm volatile("cp.async.commit_group;" ::: "memory");
}
template <int NW>
__device__ __forceinline__ void cp_wait() {
    asm volatile("cp.async.wait_group %0;" :: "n"(NW) : "memory");
}

// -------- Kernel 1: per-node transform, cp.async double-buffered staging --------
__global__ __launch_bounds__(NT, 5) void node_kernel(const float* __restrict__ x,
                                                     const float* __restrict__ W,
                                                     const float* __restrict__ att_src,
                                                     const float* __restrict__ att_dst,
                                                     int N) {
    __shared__ __align__(16) float Ws[IN_F * HC];      // 8KB
    __shared__ __align__(16) float xs[2][NT * XPAD];   // 2 x 18.4KB
    __shared__ float s_att[2 * HC];

    int tid = threadIdx.x;
    int n0 = blockIdx.x * NT;
    int n = n0 + tid;
    int valid = min(NT, N - n0);

    // Per-thread staging slots: idx = q*NT+tid -> row r=idx>>3, col c=idx&7
    int rr[8], cc[8];
#pragma unroll
    for (int q = 0; q < 8; q++) {
        int idx = q * NT + tid;
        rr[q] = idx >> 3;
        cc[q] = idx & 7;
    }

    // Prologue: kick off tile 0 immediately (DRAM latency overlaps W load)
#pragma unroll
    for (int q = 0; q < 8; q++) {
        if (rr[q] < valid)
            cp16((unsigned)__cvta_generic_to_shared(&xs[0][rr[q] * XPAD + cc[q] * 4]),
                 x + (size_t)(n0 + rr[q]) * IN_F + cc[q] * 4);
    }
    cp_commit();

    {
        const float4* Wg = (const float4*)W;
        float4* Wsv = (float4*)Ws;
        for (int i = tid; i < IN_F * HC / 4; i += NT) Wsv[i] = Wg[i];
    }
    if (tid < HC) { s_att[tid] = att_src[tid]; s_att[HC + tid] = att_dst[tid]; }

    float acc[HC];
#pragma unroll
    for (int j = 0; j < HC; j++) acc[j] = 0.f;

#pragma unroll
    for (int kt = 0; kt < NTILES; kt++) {
        // Issue next tile into the other buffer
        if (kt + 1 < NTILES) {
#pragma unroll
            for (int q = 0; q < 8; q++) {
                if (rr[q] < valid)
                    cp16((unsigned)__cvta_generic_to_shared(&xs[(kt + 1) & 1][rr[q] * XPAD + cc[q] * 4]),
                         x + (size_t)(n0 + rr[q]) * IN_F + (kt + 1) * KT + cc[q] * 4);
            }
            cp_commit();
            cp_wait<1>();   // current tile (kt) complete; kt+1 may be in flight
        } else {
            cp_wait<0>();
        }
        __syncthreads();

        if (n < N) {
            const float* xr = &xs[kt & 1][tid * XPAD];
#pragma unroll
            for (int q = 0; q < KT / 4; q++) {
                float4 xv = *(const float4*)&xr[4 * q];
                int kb = kt * KT + 4 * q;
                const float4* wr = (const float4*)&Ws[kb * HC];
#pragma unroll
                for (int kk = 0; kk < 4; kk++) {
                    float xk = (kk == 0) ? xv.x : (kk == 1) ? xv.y : (kk == 2) ? xv.z : xv.w;
                    float4 w0 = wr[kk * 4 + 0];
                    float4 w1 = wr[kk * 4 + 1];
                    float4 w2 = wr[kk * 4 + 2];
                    float4 w3 = wr[kk * 4 + 3];
                    acc[0]  = fmaf(xk, w0.x, acc[0]);
                    acc[1]  = fmaf(xk, w0.y, acc[1]);
                    acc[2]  = fmaf(xk, w0.z, acc[2]);
                    acc[3]  = fmaf(xk, w0.w, acc[3]);
                    acc[4]  = fmaf(xk, w1.x, acc[4]);
                    acc[5]  = fmaf(xk, w1.y, acc[5]);
                    acc[6]  = fmaf(xk, w1.z, acc[6]);
                    acc[7]  = fmaf(xk, w1.w, acc[7]);
                    acc[8]  = fmaf(xk, w2.x, acc[8]);
                    acc[9]  = fmaf(xk, w2.y, acc[9]);
                    acc[10] = fmaf(xk, w2.z, acc[10]);
                    acc[11] = fmaf(xk, w2.w, acc[11]);
                    acc[12] = fmaf(xk, w3.x, acc[12]);
                    acc[13] = fmaf(xk, w3.y, acc[13]);
                    acc[14] = fmaf(xk, w3.z, acc[14]);
                    acc[15] = fmaf(xk, w3.w, acc[15]);
                }
            }
        }
        __syncthreads();   // all readers done before this buffer is re-filled
    }

    if (n >= N) return;

    float as[HEADS], ad[HEADS];
#pragma unroll
    for (int hh = 0; hh < HEADS; hh++) {
        as[hh] = acc[2 * hh] * s_att[2 * hh] + acc[2 * hh + 1] * s_att[2 * hh + 1];
        ad[hh] = acc[2 * hh] * s_att[HC + 2 * hh] + acc[2 * hh + 1] * s_att[HC + 2 * hh + 1];
    }

    // packed src struct: per q-block {asrc[2q], asrc[2q+1], h[4q..4q+3] fp16}
#pragma unroll
    for (int q = 0; q < 4; q++) {
        uint4 pk;
        pk.x = __float_as_uint(as[2 * q]);
        pk.y = __float_as_uint(as[2 * q + 1]);
        __half2 t0 = __floats2half2_rn(acc[4 * q],     acc[4 * q + 1]);
        __half2 t1 = __floats2half2_rn(acc[4 * q + 2], acc[4 * q + 3]);
        pk.z = *(unsigned*)&t0;
        pk.w = *(unsigned*)&t1;
        g_pack[(size_t)n * 4 + q] = pk;
    }

    *(float4*)(g_adst + (size_t)n * HEADS)     = make_float4(ad[0], ad[1], ad[2], ad[3]);
    *(float4*)(g_adst + (size_t)n * HEADS + 4) = make_float4(ad[4], ad[5], ad[6], ad[7]);

    float p[HEADS];
#pragma unroll
    for (int hh = 0; hh < HEADS; hh++) p[hh] = fexp(leaky(as[hh] + ad[hh]));

    float* accp = g_acc + (size_t)n * 24;
#pragma unroll
    for (int q = 0; q < 4; q++) {
        *(float4*)(accp + 4 * q) = make_float4(p[2 * q] * acc[4 * q],
                                               p[2 * q] * acc[4 * q + 1],
                                               p[2 * q + 1] * acc[4 * q + 2],
                                               p[2 * q + 1] * acc[4 * q + 3]);
    }
    *(float4*)(accp + 16) = make_float4(p[0], p[1], p[2], p[3]);
    *(float4*)(accp + 20) = make_float4(p[4], p[5], p[6], p[7]);
}

// -------- Kernel 2: per-edge gather + fast-exp + scatter (vector red) --------
// Four threads per edge: thread q handles heads 2q, 2q+1. One 16B src gather.
__global__ __launch_bounds__(256) void edge_kernel(const int* __restrict__ ei, int E) {
    int t = blockIdx.x * blockDim.x + threadIdx.x;
    int e = t >> 2;
    if (e >= E) return;
    int q = t & 3;
    int s = __ldg(&ei[e]);
    int d = __ldg(&ei[E + e]);

    uint4 pk = *(const uint4*)(g_pack + (size_t)s * 4 + q);
    float2 b = *(const float2*)(g_adst + (size_t)d * HEADS + 2 * q);
    float p0 = fexp(leaky(__uint_as_float(pk.x) + b.x));
    float p1 = fexp(leaky(__uint_as_float(pk.y) + b.y));
    float2 f01 = __half22float2(*(__half2*)&pk.z);
    float2 f23 = __half22float2(*(__half2*)&pk.w);

    float* accp = g_acc + (size_t)d * 24;
    asm volatile("red.global.add.v4.f32 [%0], {%1, %2, %3, %4};"
                 :: "l"(accp + 4 * q),
                    "f"(p0 * f01.x), "f"(p0 * f01.y),
                    "f"(p1 * f23.x), "f"(p1 * f23.y) : "memory");

    float pp0 = __shfl_xor_sync(0xffffffffu, p0, 1);
    float pp1 = __shfl_xor_sync(0xffffffffu, p1, 1);
    if ((q & 1) == 0) {
        asm volatile("red.global.add.v4.f32 [%0], {%1, %2, %3, %4};"
                     :: "l"(accp + 16 + 2 * q),
                        "f"(p0), "f"(p1), "f"(pp0), "f"(pp1) : "memory");
    }
}

// -------- Kernel 3: normalize + bias + FC --------
__global__ __launch_bounds__(256) void out_kernel(const float* __restrict__ bias_gat,
                                                  const float* __restrict__ W_fc,
                                                  const float* __restrict__ b_fc,
                                                  float* __restrict__ out, int N) {
    int n = blockIdx.x * blockDim.x + threadIdx.x;
    if (n >= N) return;
    const float4* ap = (const float4*)(g_acc + (size_t)n * 24);
    float4 s0 = ap[0], s1 = ap[1], s2 = ap[2], s3 = ap[3];
    float4 z0 = ap[4], z1 = ap[5];
    float S[16] = { s0.x, s0.y, s0.z, s0.w, s1.x, s1.y, s1.z, s1.w,
                    s2.x, s2.y, s2.z, s2.w, s3.x, s3.y, s3.z, s3.w };
    float Z[8]  = { z0.x, z0.y, z0.z, z0.w, z1.x, z1.y, z1.z, z1.w };

    float o0 = __ldg(&b_fc[0]), o1 = __ldg(&b_fc[1]);
#pragma unroll
    for (int hh = 0; hh < 8; hh++) {
        float inv = 1.f / Z[hh];   // Z >= exp(self-loop) > 0 always
        float g0 = S[2 * hh] * inv + __ldg(&bias_gat[2 * hh]);
        float g1 = S[2 * hh + 1] * inv + __ldg(&bias_gat[2 * hh + 1]);
        o0 += g0 * __ldg(&W_fc[(2 * hh) * 2 + 0]) + g1 * __ldg(&W_fc[(2 * hh + 1) * 2 + 0]);
        o1 += g0 * __ldg(&W_fc[(2 * hh) * 2 + 1]) + g1 * __ldg(&W_fc[(2 * hh + 1) * 2 + 1]);
    }
    ((float2*)out)[n] = make_float2(o0, o1);
}

extern "C" void kernel_launch(void* const* d_in, const int* in_sizes, int n_in,
                              void* d_out, int out_size) {
    const float* x        = (const float*)d_in[0];
    const int*   ei       = (const int*)d_in[1];   // int32 (JAX x64 disabled)
    // d_in[2] = edge_attr: unused (GATConv built without edge_dim)
    const float* W        = (const float*)d_in[3];
    const float* att_src  = (const float*)d_in[4];
    const float* att_dst  = (const float*)d_in[5];
    const float* bias_gat = (const float*)d_in[6];
    const float* W_fc     = (const float*)d_in[7];
    const float* b_fc     = (const float*)d_in[8];

    int N = in_sizes[0] / IN_F;
    int E = in_sizes[1] / 2;

    node_kernel<<<(N + NT - 1) / NT, NT>>>(x, W, att_src, att_dst, N);
    long long tthreads = 4LL * E;
    edge_kernel<<<(int)((tthreads + 255) / 256), 256>>>(ei, E);
    out_kernel<<<(N + 255) / 256, 256>>>(bias_gat, W_fc, b_fc, (float*)d_out, N);
}